// round 14
// baseline (speedup 1.0000x reference)
#include <cuda_runtime.h>
#include <cuda_fp16.h>
#include <cooperative_groups.h>
#include <math.h>
#include <stdint.h>

namespace cg = cooperative_groups;

#define NMAX 50000
#define EMAX 800000
#define D 128
#define PRE_BLOCKS 592

// ---------------- scratch (static device globals; no allocation) -------------
__device__ int   g_counts[NMAX];
__device__ int   g_offsets[NMAX];
__device__ int   g_cursor[NMAX];
__device__ int   g_total;
__device__ int   g_adj[EMAX];
__device__ float g_dis[NMAX];
__device__ __half g_bufG[NMAX * D];  // fp16 message buffer (gather side)
__device__ __half g_bufH[NMAX * D];  // fp16 activations
__device__ __half g_Wt[3][D * D];    // W transposed [n][k], fp16

// ---------------- PTX helpers ------------------------------------------------
__device__ __forceinline__ uint32_t smem_u32(const void* p) {
    uint32_t a;
    asm("{ .reg .u64 t; cvta.to.shared.u64 t, %1; cvt.u32.u64 %0, t; }" : "=r"(a) : "l"(p));
    return a;
}

__device__ __forceinline__ void ldsm_x4(uint32_t* r, uint32_t addr) {
    asm volatile("ldmatrix.sync.aligned.m8n8.x4.shared.b16 {%0,%1,%2,%3}, [%4];"
        : "=r"(r[0]), "=r"(r[1]), "=r"(r[2]), "=r"(r[3]) : "r"(addr));
}

__device__ __forceinline__ void mma_fp16(float* c, const uint32_t* a, uint32_t b0, uint32_t b1) {
    asm volatile(
        "mma.sync.aligned.m16n8k16.row.col.f32.f16.f16.f32 "
        "{%0,%1,%2,%3}, {%4,%5,%6,%7}, {%8,%9}, {%0,%1,%2,%3};"
        : "+f"(c[0]), "+f"(c[1]), "+f"(c[2]), "+f"(c[3])
        : "r"(a[0]), "r"(a[1]), "r"(a[2]), "r"(a[3]), "r"(b0), "r"(b1));
}

__device__ __forceinline__ uint2 pack_fp16(float4 v) {
    __half hx = __float2half_rn(v.x);
    __half hy = __float2half_rn(v.y);
    __half hz = __float2half_rn(v.z);
    __half hw = __float2half_rn(v.w);
    uint2 p;
    p.x = ((uint32_t)__half_as_ushort(hy) << 16) | __half_as_ushort(hx);
    p.y = ((uint32_t)__half_as_ushort(hw) << 16) | __half_as_ushort(hz);
    return p;
}

// ---------------- cooperative preprocessing (replaces 4 kernels) -------------
// A: zero counts + W prep;  B: count;  C: scan (dis/offsets/cursors);  D: fill
__global__ void __launch_bounds__(256) k_pre(
    const int* __restrict__ src, const int* __restrict__ dst,
    int n, int e,
    const float* __restrict__ W0, const float* __restrict__ W1,
    const float* __restrict__ W2)
{
    cg::grid_group grid = cg::this_grid();
    int gtid = blockIdx.x * 256 + threadIdx.x;
    int gsz  = gridDim.x * 256;

    // ---- A: zero counts + total, W transpose to fp16 ----
    if (gtid == 0) g_total = 0;
    for (int i = gtid; i < n; i += gsz) g_counts[i] = 0;
    for (int i = gtid; i < 3 * D * D; i += gsz) {
        int layer = i >> 14;            // /16384
        int nn    = (i >> 7) & 127;
        int k     = i & 127;
        const float* W = (layer == 0) ? W0 : (layer == 1) ? W1 : W2;
        g_Wt[layer][nn * D + k] = __float2half_rn(W[k * D + nn]);
    }
    grid.sync();

    // ---- B: degree count ----
    for (int i = gtid; i < e; i += gsz) atomicAdd(&g_counts[dst[i]], 1);
    grid.sync();

    // ---- C: scan (256-chunk per block, atomic global base; non-monotonic OK) --
    {
        __shared__ int warpsum[8];
        __shared__ int sbase;
        int tid = threadIdx.x, lane = tid & 31, wid = tid >> 5;
        int i = blockIdx.x * 256 + tid;
        if (blockIdx.x * 256 < n) {
            int v = (i < n) ? g_counts[i] : 0;
            if (i < n) g_dis[i] = rsqrtf((float)(v + 1));   // +1 self loop
            int s = v;
#pragma unroll
            for (int o = 1; o < 32; o <<= 1) {
                int t = __shfl_up_sync(0xFFFFFFFFu, s, o);
                if (lane >= o) s += t;
            }
            if (lane == 31) warpsum[wid] = s;
            __syncthreads();
            if (wid == 0 && lane < 8) {
                int ws = warpsum[lane];
#pragma unroll
                for (int o = 1; o < 8; o <<= 1) {
                    int t = __shfl_up_sync(0xFFu, ws, o);
                    if (lane >= o) ws += t;
                }
                warpsum[lane] = ws;
                if (lane == 7) sbase = atomicAdd(&g_total, ws);
            }
            __syncthreads();
            if (i < n) {
                int excl = sbase + ((wid > 0) ? warpsum[wid - 1] : 0) + s - v;
                g_offsets[i] = excl;
                g_cursor[i]  = excl;
            }
        }
    }
    grid.sync();

    // ---- D: CSR fill ----
    for (int i = gtid; i < e; i += gsz) {
        int p = atomicAdd(&g_cursor[dst[i]], 1);
        g_adj[p] = src[i];
    }
}

// ---------------- GEMM constants ---------------------------------------------
#define PADA 136                           // halves per row, full-width tiles
#define SMA_TILE (128 * PADA)
#define G_SMEM (2 * SMA_TILE * 2)          // A, W

// ---------------- GEMM core (fp16 single product, full-width tiles) ----------
// CONV=1: A is fp32, convert during smem load. CONV=0: A is fp16.
template <int CONV>
__global__ void __launch_bounds__(256, 2) k_gemm(
    const void* __restrict__ Avoid,
    const __half* __restrict__ Wt,
    __half* __restrict__ G, int n)
{
    extern __shared__ char smem[];
    __half* sA = (__half*)smem;
    __half* sW = sA + SMA_TILE;

    int tid  = threadIdx.x;
    int lane = tid & 31;
    int w    = tid >> 5;
    int m0 = (w >> 1) * 32;
    int n0 = (w & 1) * 64;
    int row0 = blockIdx.x * 128;

    uint32_t aA = smem_u32(sA);
    uint32_t aW = smem_u32(sW);

    int ldRow = tid >> 1;
    int ldCol = (tid & 1) * 64;
    {
        bool okA = (row0 + ldRow) < n;
        const uint4* Wg = (const uint4*)(Wt + ldRow * D + ldCol);
        if (CONV) {
            const float4* Ag = (const float4*)((const float*)Avoid + (size_t)(row0 + ldRow) * D + ldCol);
#pragma unroll
            for (int j = 0; j < 16; j++) {
                float4 v = okA ? Ag[j] : make_float4(0.f, 0.f, 0.f, 0.f);
                *(uint2*)(sA + ldRow * PADA + ldCol + 4 * j) = pack_fp16(v);
            }
        } else {
            const uint4* Ag = (const uint4*)((const __half*)Avoid + (size_t)(row0 + ldRow) * D + ldCol);
            uint4 z = make_uint4(0u, 0u, 0u, 0u);
#pragma unroll
            for (int j = 0; j < 8; j++)
                *(uint4*)(sA + ldRow * PADA + ldCol + 8 * j) = okA ? Ag[j] : z;
        }
#pragma unroll
        for (int j = 0; j < 8; j++)
            *(uint4*)(sW + ldRow * PADA + ldCol + 8 * j) = Wg[j];
    }
    __syncthreads();

    float acc[2][8][4];
#pragma unroll
    for (int mt = 0; mt < 2; mt++)
#pragma unroll
        for (int nt = 0; nt < 8; nt++)
#pragma unroll
            for (int q = 0; q < 4; q++) acc[mt][nt][q] = 0.f;

#pragma unroll
    for (int ks = 0; ks < 8; ks++) {
        int acol = ks * 16 + ((lane >> 4) << 3);
        int lrow = lane & 15;
        uint32_t af[2][4];
        ldsm_x4(af[0], aA + (uint32_t)(((m0      + lrow) * PADA + acol) * 2));
        ldsm_x4(af[1], aA + (uint32_t)(((m0 + 16 + lrow) * PADA + acol) * 2));
        uint32_t bf_[4][4];
#pragma unroll
        for (int bt = 0; bt < 4; bt++)
            ldsm_x4(bf_[bt], aW + (uint32_t)(((n0 + bt * 16 + lrow) * PADA + acol) * 2));
#pragma unroll
        for (int mt = 0; mt < 2; mt++)
#pragma unroll
            for (int bt = 0; bt < 4; bt++) {
                mma_fp16(acc[mt][2 * bt],     af[mt], bf_[bt][0], bf_[bt][2]);
                mma_fp16(acc[mt][2 * bt + 1], af[mt], bf_[bt][1], bf_[bt][3]);
            }
    }

#pragma unroll
    for (int mt = 0; mt < 2; mt++) {
        int r0 = row0 + m0 + mt * 16 + (lane >> 2);
        int r1 = r0 + 8;
        float d0 = (r0 < n) ? g_dis[r0] : 0.f;
        float d1 = (r1 < n) ? g_dis[r1] : 0.f;
#pragma unroll
        for (int nt = 0; nt < 8; nt++) {
            int col = n0 + nt * 8 + (lane & 3) * 2;
            if (r0 < n)
                *(__half2*)(G + (size_t)r0 * D + col) =
                    __floats2half2_rn(acc[mt][nt][0] * d0, acc[mt][nt][1] * d0);
            if (r1 < n)
                *(__half2*)(G + (size_t)r1 * D + col) =
                    __floats2half2_rn(acc[mt][nt][2] * d1, acc[mt][nt][3] * d1);
        }
    }
}

// ---------------- aggregation core (fp32 accum over fp16 gathers) ------------
__device__ __forceinline__ float4 agg_node(const uint2* __restrict__ G8,
                                           int node, int lane) {
    uint2 sr = G8[(size_t)node * 32 + lane];     // self term
    float2 s0 = __half22float2(*(const __half2*)&sr.x);
    float2 s1 = __half22float2(*(const __half2*)&sr.y);
    float4 acc = make_float4(s0.x, s0.y, s1.x, s1.y);

    int start = g_offsets[node];
    int cnt   = g_counts[node];
    int e = 0;
    for (; e + 4 <= cnt; e += 4) {
        int i0 = g_adj[start + e + 0];
        int i1 = g_adj[start + e + 1];
        int i2 = g_adj[start + e + 2];
        int i3 = g_adj[start + e + 3];
        uint2 r0 = G8[(size_t)i0 * 32 + lane];
        uint2 r1 = G8[(size_t)i1 * 32 + lane];
        uint2 r2 = G8[(size_t)i2 * 32 + lane];
        uint2 r3 = G8[(size_t)i3 * 32 + lane];
        float2 a, b;
        a = __half22float2(*(const __half2*)&r0.x); b = __half22float2(*(const __half2*)&r0.y);
        acc.x += a.x; acc.y += a.y; acc.z += b.x; acc.w += b.y;
        a = __half22float2(*(const __half2*)&r1.x); b = __half22float2(*(const __half2*)&r1.y);
        acc.x += a.x; acc.y += a.y; acc.z += b.x; acc.w += b.y;
        a = __half22float2(*(const __half2*)&r2.x); b = __half22float2(*(const __half2*)&r2.y);
        acc.x += a.x; acc.y += a.y; acc.z += b.x; acc.w += b.y;
        a = __half22float2(*(const __half2*)&r3.x); b = __half22float2(*(const __half2*)&r3.y);
        acc.x += a.x; acc.y += a.y; acc.z += b.x; acc.w += b.y;
    }
    for (; e < cnt; e++) {
        int s = g_adj[start + e];
        uint2 r = G8[(size_t)s * 32 + lane];
        float2 a = __half22float2(*(const __half2*)&r.x);
        float2 b = __half22float2(*(const __half2*)&r.y);
        acc.x += a.x; acc.y += a.y; acc.z += b.x; acc.w += b.y;
    }
    return acc;
}

// intermediate layers: fp16 activation out, relu
__global__ void k_aggregate_h(const __half* __restrict__ G,
                              const float* __restrict__ bias,
                              __half* __restrict__ out, int n) {
    int warp = (blockIdx.x * blockDim.x + threadIdx.x) >> 5;
    if (warp >= n) return;
    int lane = threadIdx.x & 31;

    float4 acc = agg_node((const uint2*)G, warp, lane);
    float ds = g_dis[warp];
    float4 b4 = ((const float4*)bias)[lane];
    float4 o;
    o.x = fmaxf(fmaf(ds, acc.x, b4.x), 0.f);
    o.y = fmaxf(fmaf(ds, acc.y, b4.y), 0.f);
    o.z = fmaxf(fmaf(ds, acc.z, b4.z), 0.f);
    o.w = fmaxf(fmaf(ds, acc.w, b4.w), 0.f);
    uint2 p;
    *(__half2*)&p.x = __floats2half2_rn(o.x, o.y);
    *(__half2*)&p.y = __floats2half2_rn(o.z, o.w);
    ((uint2*)out)[(size_t)warp * 32 + lane] = p;
}

// final layer: fp32 out, no relu
__global__ void k_aggregate_f(const __half* __restrict__ G,
                              const float* __restrict__ bias,
                              float* __restrict__ out, int n) {
    int warp = (blockIdx.x * blockDim.x + threadIdx.x) >> 5;
    if (warp >= n) return;
    int lane = threadIdx.x & 31;

    float4 acc = agg_node((const uint2*)G, warp, lane);
    float ds = g_dis[warp];
    float4 b4 = ((const float4*)bias)[lane];
    float4 o;
    o.x = fmaf(ds, acc.x, b4.x);
    o.y = fmaf(ds, acc.y, b4.y);
    o.z = fmaf(ds, acc.z, b4.z);
    o.w = fmaf(ds, acc.w, b4.w);
    ((float4*)out)[(size_t)warp * 32 + lane] = o;
}

// ---------------- launch -----------------------------------------------------
extern "C" void kernel_launch(void* const* d_in, const int* in_sizes, int n_in,
                              void* d_out, int out_size) {
    const float* x  = (const float*)d_in[0];
    const int*   ei = (const int*)d_in[1];
    const float* W0 = (const float*)d_in[2];
    const float* b0 = (const float*)d_in[3];
    const float* W1 = (const float*)d_in[4];
    const float* b1 = (const float*)d_in[5];
    const float* W2 = (const float*)d_in[6];
    const float* b2 = (const float*)d_in[7];

    int n = in_sizes[0] / D;
    int e = in_sizes[1] / 2;
    const int* src = ei;
    const int* dst = ei + e;

    __half* bufG = nullptr; __half* bufH = nullptr;
    __half* wt = nullptr;
    cudaGetSymbolAddress((void**)&bufG, g_bufG);
    cudaGetSymbolAddress((void**)&bufH, g_bufH);
    cudaGetSymbolAddress((void**)&wt, g_Wt);
    float* out = (float*)d_out;

    cudaFuncSetAttribute(k_gemm<1>, cudaFuncAttributeMaxDynamicSharedMemorySize, G_SMEM);
    cudaFuncSetAttribute(k_gemm<0>, cudaFuncAttributeMaxDynamicSharedMemorySize, G_SMEM);

    // cooperative preprocessing (one kernel replaces setup/count/scan/fill)
    {
        void* args[] = { (void*)&src, (void*)&dst, (void*)&n, (void*)&e,
                         (void*)&W0, (void*)&W1, (void*)&W2 };
        cudaLaunchCooperativeKernel((void*)k_pre, dim3(PRE_BLOCKS), dim3(256),
                                    args, 0, (cudaStream_t)0);
    }

    int ggemm = (n + 127) / 128;
    int gagg  = (n * 32 + 255) / 256;

    k_gemm<1>    <<<ggemm, 256, G_SMEM>>>(x, wt + 0 * D * D, bufG, n);
    k_aggregate_h<<<gagg, 256>>>(bufG, b0, bufH, n);
    k_gemm<0>    <<<ggemm, 256, G_SMEM>>>(bufH, wt + 1 * D * D, bufG, n);
    k_aggregate_h<<<gagg, 256>>>(bufG, b1, bufH, n);
    k_gemm<0>    <<<ggemm, 256, G_SMEM>>>(bufH, wt + 2 * D * D, bufG, n);
    k_aggregate_f<<<gagg, 256>>>(bufG, b2, out, n);
}

// round 15
// speedup vs baseline: 1.0245x; 1.0245x over previous
#include <cuda_runtime.h>
#include <cuda_fp16.h>
#include <math.h>
#include <stdint.h>

#define NMAX 50000
#define EMAX 800000
#define D 128

// ---------------- scratch (static device globals; no allocation) -------------
__device__ int   g_counts[NMAX];
__device__ int   g_offsets[NMAX];
__device__ int   g_cursor[NMAX];     // pre-initialized to offsets by k_scan
__device__ int   g_total;            // global base cursor for scan
__device__ int   g_adj[EMAX];
__device__ float g_dis[NMAX];
__device__ __half g_bufG[NMAX * D];  // fp16 message buffer (gather side)
__device__ __half g_bufH[NMAX * D];  // fp16 activations
__device__ __half g_Wt[3][D * D];    // W transposed [n][k], fp16

// ---------------- PTX helpers ------------------------------------------------
__device__ __forceinline__ uint32_t smem_u32(const void* p) {
    uint32_t a;
    asm("{ .reg .u64 t; cvta.to.shared.u64 t, %1; cvt.u32.u64 %0, t; }" : "=r"(a) : "l"(p));
    return a;
}

__device__ __forceinline__ void ldsm_x4(uint32_t* r, uint32_t addr) {
    asm volatile("ldmatrix.sync.aligned.m8n8.x4.shared.b16 {%0,%1,%2,%3}, [%4];"
        : "=r"(r[0]), "=r"(r[1]), "=r"(r[2]), "=r"(r[3]) : "r"(addr));
}

__device__ __forceinline__ void mma_fp16(float* c, const uint32_t* a, uint32_t b0, uint32_t b1) {
    asm volatile(
        "mma.sync.aligned.m16n8k16.row.col.f32.f16.f16.f32 "
        "{%0,%1,%2,%3}, {%4,%5,%6,%7}, {%8,%9}, {%0,%1,%2,%3};"
        : "+f"(c[0]), "+f"(c[1]), "+f"(c[2]), "+f"(c[3])
        : "r"(a[0]), "r"(a[1]), "r"(a[2]), "r"(a[3]), "r"(b0), "r"(b1));
}

__device__ __forceinline__ uint2 pack_fp16(float4 v) {
    __half hx = __float2half_rn(v.x);
    __half hy = __float2half_rn(v.y);
    __half hz = __float2half_rn(v.z);
    __half hw = __float2half_rn(v.w);
    uint2 p;
    p.x = ((uint32_t)__half_as_ushort(hy) << 16) | __half_as_ushort(hx);
    p.y = ((uint32_t)__half_as_ushort(hw) << 16) | __half_as_ushort(hz);
    return p;
}

// ---------------- setup: zero counts + total, prep W (one launch) ------------
__global__ void k_setup(int n, int gn,
                        const float* __restrict__ W0,
                        const float* __restrict__ W1,
                        const float* __restrict__ W2) {
    int b = blockIdx.x;
    if (b == 0 && threadIdx.x == 0) g_total = 0;
    if (b < gn) {
        int i = b * 256 + threadIdx.x;
        if (i < n) g_counts[i] = 0;
    } else {
        int id = b - gn;                 // 0..191
        int layer = id >> 6;             // /64
        int pair  = id & 63;
        int nn = pair * 2 + (threadIdx.x >> 7);
        int k  = threadIdx.x & 127;
        const float* W = (layer == 0) ? W0 : (layer == 1) ? W1 : W2;
        g_Wt[layer][nn * D + k] = __float2half_rn(W[k * D + nn]);
    }
}

// ---------------- preprocessing (1 edge per thread — R12 proven best) --------
__global__ void k_count(const int* __restrict__ dst, int e) {
    int i = blockIdx.x * blockDim.x + threadIdx.x;
    if (i < e) atomicAdd(&g_counts[dst[i]], 1);
}

// one-pass scan: per-block scan + atomic block base (offsets non-monotonic
// across blocks — fine, CSR only needs disjoint ranges). Emits dis + cursors.
__global__ void __launch_bounds__(1024) k_scan(int n) {
    __shared__ int warpsum[32];
    __shared__ int sbase;
    int tid = threadIdx.x, lane = tid & 31, wid = tid >> 5;
    int i = blockIdx.x * 1024 + tid;
    int v = (i < n) ? g_counts[i] : 0;
    if (i < n) g_dis[i] = rsqrtf((float)(v + 1));   // +1 self loop

    int s = v;
#pragma unroll
    for (int o = 1; o < 32; o <<= 1) {
        int t = __shfl_up_sync(0xFFFFFFFFu, s, o);
        if (lane >= o) s += t;
    }
    if (lane == 31) warpsum[wid] = s;
    __syncthreads();
    if (wid == 0) {
        int ws = warpsum[lane];
#pragma unroll
        for (int o = 1; o < 32; o <<= 1) {
            int t = __shfl_up_sync(0xFFFFFFFFu, ws, o);
            if (lane >= o) ws += t;
        }
        warpsum[lane] = ws;
        if (lane == 31) sbase = atomicAdd(&g_total, ws);
    }
    __syncthreads();
    if (i < n) {
        int excl = sbase + ((wid > 0) ? warpsum[wid - 1] : 0) + s - v;
        g_offsets[i] = excl;
        g_cursor[i]  = excl;
    }
}

__global__ void k_fill(const int* __restrict__ src, const int* __restrict__ dst, int e) {
    int i = blockIdx.x * blockDim.x + threadIdx.x;
    if (i < e) {
        int p = atomicAdd(&g_cursor[dst[i]], 1);
        g_adj[p] = src[i];
    }
}

// ---------------- GEMM constants ---------------------------------------------
#define PADA 136                           // halves per row, full-width tiles
#define SMA_TILE (128 * PADA)
#define G_SMEM (2 * SMA_TILE * 2)          // A, W

// ---------------- GEMM core: 4 warps, 64x64 warp tiles -----------------------
// 128x128 block tile, 128 threads. Each A/W element ldmatrix'd only 2x
// (vs 2x/4x with 8 warps); 32 independent MMAs per ks-step for ILP.
// CONV=1: A fp32, convert during smem load. CONV=0: A fp16.
template <int CONV>
__global__ void __launch_bounds__(128) k_gemm(
    const void* __restrict__ Avoid,
    const __half* __restrict__ Wt,
    __half* __restrict__ G, int n)
{
    extern __shared__ char smem[];
    __half* sA = (__half*)smem;
    __half* sW = sA + SMA_TILE;

    int tid  = threadIdx.x;
    int lane = tid & 31;
    int w    = tid >> 5;                // 0..3
    int m0 = (w >> 1) * 64;
    int n0 = (w & 1) * 64;
    int row0 = blockIdx.x * 128;

    uint32_t aA = smem_u32(sA);
    uint32_t aW = smem_u32(sW);

    // load tiles: one row per thread (128 rows / 128 threads)
    {
        int r = tid;
        bool okA = (row0 + r) < n;
        const uint4* Wg = (const uint4*)(Wt + r * D);
        if (CONV) {
            const float4* Ag = (const float4*)((const float*)Avoid + (size_t)(row0 + r) * D);
#pragma unroll
            for (int j = 0; j < 32; j++) {
                float4 v = okA ? Ag[j] : make_float4(0.f, 0.f, 0.f, 0.f);
                *(uint2*)(sA + r * PADA + 4 * j) = pack_fp16(v);
            }
        } else {
            const uint4* Ag = (const uint4*)((const __half*)Avoid + (size_t)(row0 + r) * D);
            uint4 z = make_uint4(0u, 0u, 0u, 0u);
#pragma unroll
            for (int j = 0; j < 16; j++)
                *(uint4*)(sA + r * PADA + 8 * j) = okA ? Ag[j] : z;
        }
#pragma unroll
        for (int j = 0; j < 16; j++)
            *(uint4*)(sW + r * PADA + 8 * j) = Wg[j];
    }
    __syncthreads();

    float acc[4][8][4];
#pragma unroll
    for (int mt = 0; mt < 4; mt++)
#pragma unroll
        for (int nt = 0; nt < 8; nt++)
#pragma unroll
            for (int q = 0; q < 4; q++) acc[mt][nt][q] = 0.f;

#pragma unroll
    for (int ks = 0; ks < 8; ks++) {
        int acol = ks * 16 + ((lane >> 4) << 3);
        int lrow = lane & 15;
        uint32_t af[4][4];
#pragma unroll
        for (int mt = 0; mt < 4; mt++)
            ldsm_x4(af[mt], aA + (uint32_t)(((m0 + mt * 16 + lrow) * PADA + acol) * 2));
        uint32_t bf_[4][4];
#pragma unroll
        for (int bt = 0; bt < 4; bt++)
            ldsm_x4(bf_[bt], aW + (uint32_t)(((n0 + bt * 16 + lrow) * PADA + acol) * 2));
#pragma unroll
        for (int mt = 0; mt < 4; mt++)
#pragma unroll
            for (int bt = 0; bt < 4; bt++) {
                mma_fp16(acc[mt][2 * bt],     af[mt], bf_[bt][0], bf_[bt][2]);
                mma_fp16(acc[mt][2 * bt + 1], af[mt], bf_[bt][1], bf_[bt][3]);
            }
    }

    // ---- epilogue: scale rows by dis, store fp16 ----
#pragma unroll
    for (int mt = 0; mt < 4; mt++) {
        int r0 = row0 + m0 + mt * 16 + (lane >> 2);
        int r1 = r0 + 8;
        float d0 = (r0 < n) ? g_dis[r0] : 0.f;
        float d1 = (r1 < n) ? g_dis[r1] : 0.f;
#pragma unroll
        for (int nt = 0; nt < 8; nt++) {
            int col = n0 + nt * 8 + (lane & 3) * 2;
            if (r0 < n)
                *(__half2*)(G + (size_t)r0 * D + col) =
                    __floats2half2_rn(acc[mt][nt][0] * d0, acc[mt][nt][1] * d0);
            if (r1 < n)
                *(__half2*)(G + (size_t)r1 * D + col) =
                    __floats2half2_rn(acc[mt][nt][2] * d1, acc[mt][nt][3] * d1);
        }
    }
}

// ---------------- aggregation core (fp32 accum over fp16 gathers) ------------
__device__ __forceinline__ float4 agg_node(const uint2* __restrict__ G8,
                                           int node, int lane) {
    uint2 sr = G8[(size_t)node * 32 + lane];     // self term
    float2 s0 = __half22float2(*(const __half2*)&sr.x);
    float2 s1 = __half22float2(*(const __half2*)&sr.y);
    float4 acc = make_float4(s0.x, s0.y, s1.x, s1.y);

    int start = g_offsets[node];
    int cnt   = g_counts[node];
    int e = 0;
    for (; e + 4 <= cnt; e += 4) {
        int i0 = g_adj[start + e + 0];
        int i1 = g_adj[start + e + 1];
        int i2 = g_adj[start + e + 2];
        int i3 = g_adj[start + e + 3];
        uint2 r0 = G8[(size_t)i0 * 32 + lane];
        uint2 r1 = G8[(size_t)i1 * 32 + lane];
        uint2 r2 = G8[(size_t)i2 * 32 + lane];
        uint2 r3 = G8[(size_t)i3 * 32 + lane];
        float2 a, b;
        a = __half22float2(*(const __half2*)&r0.x); b = __half22float2(*(const __half2*)&r0.y);
        acc.x += a.x; acc.y += a.y; acc.z += b.x; acc.w += b.y;
        a = __half22float2(*(const __half2*)&r1.x); b = __half22float2(*(const __half2*)&r1.y);
        acc.x += a.x; acc.y += a.y; acc.z += b.x; acc.w += b.y;
        a = __half22float2(*(const __half2*)&r2.x); b = __half22float2(*(const __half2*)&r2.y);
        acc.x += a.x; acc.y += a.y; acc.z += b.x; acc.w += b.y;
        a = __half22float2(*(const __half2*)&r3.x); b = __half22float2(*(const __half2*)&r3.y);
        acc.x += a.x; acc.y += a.y; acc.z += b.x; acc.w += b.y;
    }
    for (; e < cnt; e++) {
        int s = g_adj[start + e];
        uint2 r = G8[(size_t)s * 32 + lane];
        float2 a = __half22float2(*(const __half2*)&r.x);
        float2 b = __half22float2(*(const __half2*)&r.y);
        acc.x += a.x; acc.y += a.y; acc.z += b.x; acc.w += b.y;
    }
    return acc;
}

// intermediate layers: fp16 activation out, relu
__global__ void k_aggregate_h(const __half* __restrict__ G,
                              const float* __restrict__ bias,
                              __half* __restrict__ out, int n) {
    int warp = (blockIdx.x * blockDim.x + threadIdx.x) >> 5;
    if (warp >= n) return;
    int lane = threadIdx.x & 31;

    float4 acc = agg_node((const uint2*)G, warp, lane);
    float ds = g_dis[warp];
    float4 b4 = ((const float4*)bias)[lane];
    float4 o;
    o.x = fmaxf(fmaf(ds, acc.x, b4.x), 0.f);
    o.y = fmaxf(fmaf(ds, acc.y, b4.y), 0.f);
    o.z = fmaxf(fmaf(ds, acc.z, b4.z), 0.f);
    o.w = fmaxf(fmaf(ds, acc.w, b4.w), 0.f);
    uint2 p;
    *(__half2*)&p.x = __floats2half2_rn(o.x, o.y);
    *(__half2*)&p.y = __floats2half2_rn(o.z, o.w);
    ((uint2*)out)[(size_t)warp * 32 + lane] = p;
}

// final layer: fp32 out, no relu
__global__ void k_aggregate_f(const __half* __restrict__ G,
                              const float* __restrict__ bias,
                              float* __restrict__ out, int n) {
    int warp = (blockIdx.x * blockDim.x + threadIdx.x) >> 5;
    if (warp >= n) return;
    int lane = threadIdx.x & 31;

    float4 acc = agg_node((const uint2*)G, warp, lane);
    float ds = g_dis[warp];
    float4 b4 = ((const float4*)bias)[lane];
    float4 o;
    o.x = fmaf(ds, acc.x, b4.x);
    o.y = fmaf(ds, acc.y, b4.y);
    o.z = fmaf(ds, acc.z, b4.z);
    o.w = fmaf(ds, acc.w, b4.w);
    ((float4*)out)[(size_t)warp * 32 + lane] = o;
}

// ---------------- launch -----------------------------------------------------
extern "C" void kernel_launch(void* const* d_in, const int* in_sizes, int n_in,
                              void* d_out, int out_size) {
    const float* x  = (const float*)d_in[0];
    const int*   ei = (const int*)d_in[1];
    const float* W0 = (const float*)d_in[2];
    const float* b0 = (const float*)d_in[3];
    const float* W1 = (const float*)d_in[4];
    const float* b1 = (const float*)d_in[5];
    const float* W2 = (const float*)d_in[6];
    const float* b2 = (const float*)d_in[7];

    int n = in_sizes[0] / D;
    int e = in_sizes[1] / 2;
    const int* src = ei;
    const int* dst = ei + e;

    __half* bufG = nullptr; __half* bufH = nullptr;
    __half* wt = nullptr;
    cudaGetSymbolAddress((void**)&bufG, g_bufG);
    cudaGetSymbolAddress((void**)&bufH, g_bufH);
    cudaGetSymbolAddress((void**)&wt, g_Wt);
    float* out = (float*)d_out;

    cudaFuncSetAttribute(k_gemm<1>, cudaFuncAttributeMaxDynamicSharedMemorySize, G_SMEM);
    cudaFuncSetAttribute(k_gemm<0>, cudaFuncAttributeMaxDynamicSharedMemorySize, G_SMEM);

    int gn = (n + 255) / 256;
    int ge = (e + 255) / 256;
    int nb = (n + 1023) / 1024;

    k_setup<<<gn + 192, 256>>>(n, gn, W0, W1, W2);
    k_count<<<ge, 256>>>(dst, e);
    k_scan <<<nb, 1024>>>(n);
    k_fill <<<ge, 256>>>(src, dst, e);

    int ggemm = (n + 127) / 128;
    int gagg  = (n * 32 + 255) / 256;

    k_gemm<1>    <<<ggemm, 128, G_SMEM>>>(x, wt + 0 * D * D, bufG, n);
    k_aggregate_h<<<gagg, 256>>>(bufG, b0, bufH, n);
    k_gemm<0>    <<<ggemm, 128, G_SMEM>>>(bufH, wt + 1 * D * D, bufG, n);
    k_aggregate_h<<<gagg, 256>>>(bufG, b1, bufH, n);
    k_gemm<0>    <<<ggemm, 128, G_SMEM>>>(bufH, wt + 2 * D * D, bufG, n);
    k_aggregate_f<<<gagg, 256>>>(bufG, b2, out, n);
}

// round 16
// speedup vs baseline: 1.0699x; 1.0443x over previous
#include <cuda_runtime.h>
#include <cuda_fp16.h>
#include <math.h>
#include <stdint.h>

#define NMAX 50000
#define EMAX 800000
#define D 128

// ---------------- scratch (static device globals; no allocation) -------------
__device__ int   g_counts[NMAX];
__device__ int   g_offsets[NMAX];
__device__ int   g_cursor[NMAX];     // pre-initialized to offsets by k_scan
__device__ int   g_total;            // global base cursor for scan
__device__ int   g_adj[EMAX];
__device__ float g_dis[NMAX];
__device__ __half g_bufG[NMAX * D];  // fp16 message buffer (gather side)
__device__ __half g_bufH[NMAX * D];  // fp16 activations
__device__ __half g_Wt[3][D * D];    // W transposed [n][k], fp16

// ---------------- PTX helpers ------------------------------------------------
__device__ __forceinline__ uint32_t smem_u32(const void* p) {
    uint32_t a;
    asm("{ .reg .u64 t; cvta.to.shared.u64 t, %1; cvt.u32.u64 %0, t; }" : "=r"(a) : "l"(p));
    return a;
}

__device__ __forceinline__ void ldsm_x4(uint32_t* r, uint32_t addr) {
    asm volatile("ldmatrix.sync.aligned.m8n8.x4.shared.b16 {%0,%1,%2,%3}, [%4];"
        : "=r"(r[0]), "=r"(r[1]), "=r"(r[2]), "=r"(r[3]) : "r"(addr));
}

__device__ __forceinline__ void mma_fp16(float* c, const uint32_t* a, uint32_t b0, uint32_t b1) {
    asm volatile(
        "mma.sync.aligned.m16n8k16.row.col.f32.f16.f16.f32 "
        "{%0,%1,%2,%3}, {%4,%5,%6,%7}, {%8,%9}, {%0,%1,%2,%3};"
        : "+f"(c[0]), "+f"(c[1]), "+f"(c[2]), "+f"(c[3])
        : "r"(a[0]), "r"(a[1]), "r"(a[2]), "r"(a[3]), "r"(b0), "r"(b1));
}

__device__ __forceinline__ uint2 pack_fp16(float4 v) {
    __half hx = __float2half_rn(v.x);
    __half hy = __float2half_rn(v.y);
    __half hz = __float2half_rn(v.z);
    __half hw = __float2half_rn(v.w);
    uint2 p;
    p.x = ((uint32_t)__half_as_ushort(hy) << 16) | __half_as_ushort(hx);
    p.y = ((uint32_t)__half_as_ushort(hw) << 16) | __half_as_ushort(hz);
    return p;
}

// ---------------- setup: zero counts + total, prep W (one launch) ------------
__global__ void k_setup(int n, int gn,
                        const float* __restrict__ W0,
                        const float* __restrict__ W1,
                        const float* __restrict__ W2) {
    int b = blockIdx.x;
    if (b == 0 && threadIdx.x == 0) g_total = 0;
    if (b < gn) {
        int i = b * 256 + threadIdx.x;
        if (i < n) g_counts[i] = 0;
    } else {
        int id = b - gn;                 // 0..191
        int layer = id >> 6;             // /64
        int pair  = id & 63;
        int nn = pair * 2 + (threadIdx.x >> 7);
        int k  = threadIdx.x & 127;
        const float* W = (layer == 0) ? W0 : (layer == 1) ? W1 : W2;
        g_Wt[layer][nn * D + k] = __float2half_rn(W[k * D + nn]);
    }
}

// ---------------- preprocessing (1 edge/thread; PDL-overlapped) --------------
__global__ void k_count(const int* __restrict__ dst, int e) {
    int i = blockIdx.x * blockDim.x + threadIdx.x;
    int d = (i < e) ? dst[i] : 0;          // input prefetch pre-sync
    cudaGridDependencySynchronize();        // wait: counts zeroed by k_setup
    if (i < e) atomicAdd(&g_counts[d], 1);
}

// one-pass scan: per-block scan + atomic block base (offsets non-monotonic
// across blocks — fine, CSR only needs disjoint ranges). Emits dis + cursors.
__global__ void __launch_bounds__(1024) k_scan(int n) {
    __shared__ int warpsum[32];
    __shared__ int sbase;
    cudaGridDependencySynchronize();        // wait: counts from k_count
    int tid = threadIdx.x, lane = tid & 31, wid = tid >> 5;
    int i = blockIdx.x * 1024 + tid;
    int v = (i < n) ? g_counts[i] : 0;
    if (i < n) g_dis[i] = rsqrtf((float)(v + 1));   // +1 self loop

    int s = v;
#pragma unroll
    for (int o = 1; o < 32; o <<= 1) {
        int t = __shfl_up_sync(0xFFFFFFFFu, s, o);
        if (lane >= o) s += t;
    }
    if (lane == 31) warpsum[wid] = s;
    __syncthreads();
    if (wid == 0) {
        int ws = warpsum[lane];
#pragma unroll
        for (int o = 1; o < 32; o <<= 1) {
            int t = __shfl_up_sync(0xFFFFFFFFu, ws, o);
            if (lane >= o) ws += t;
        }
        warpsum[lane] = ws;
        if (lane == 31) sbase = atomicAdd(&g_total, ws);
    }
    __syncthreads();
    if (i < n) {
        int excl = sbase + ((wid > 0) ? warpsum[wid - 1] : 0) + s - v;
        g_offsets[i] = excl;
        g_cursor[i]  = excl;
    }
}

__global__ void k_fill(const int* __restrict__ src, const int* __restrict__ dst, int e) {
    int i = blockIdx.x * blockDim.x + threadIdx.x;
    int s = 0, d = 0;
    if (i < e) { s = src[i]; d = dst[i]; }  // input prefetch pre-sync
    cudaGridDependencySynchronize();         // wait: cursors from k_scan
    if (i < e) {
        int p = atomicAdd(&g_cursor[d], 1);
        g_adj[p] = s;
    }
}

// ---------------- GEMM constants ---------------------------------------------
#define PADA 136                           // halves per row, full-width tiles
#define SMA_TILE (128 * PADA)
#define G_SMEM (2 * SMA_TILE * 2)          // A, W

// ---------------- GEMM core (R12: 8 warps, 32x64 warp tiles) -----------------
// CONV=1: A fp32 (input x; loaded pre-sync). CONV=0: A fp16 from predecessor.
template <int CONV>
__global__ void __launch_bounds__(256, 2) k_gemm(
    const void* __restrict__ Avoid,
    const __half* __restrict__ Wt,
    __half* __restrict__ G, int n)
{
    extern __shared__ char smem[];
    __half* sA = (__half*)smem;
    __half* sW = sA + SMA_TILE;

    int tid  = threadIdx.x;
    int lane = tid & 31;
    int w    = tid >> 5;
    int m0 = (w >> 1) * 32;
    int n0 = (w & 1) * 64;
    int row0 = blockIdx.x * 128;

    uint32_t aA = smem_u32(sA);
    uint32_t aW = smem_u32(sW);

    int ldRow = tid >> 1;
    int ldCol = (tid & 1) * 64;
    bool okA = (row0 + ldRow) < n;

    if (CONV) {
        // A = x (harness input) — safe to load before the dependency sync
        const float4* Ag = (const float4*)((const float*)Avoid + (size_t)(row0 + ldRow) * D + ldCol);
#pragma unroll
        for (int j = 0; j < 16; j++) {
            float4 v = okA ? Ag[j] : make_float4(0.f, 0.f, 0.f, 0.f);
            *(uint2*)(sA + ldRow * PADA + ldCol + 4 * j) = pack_fp16(v);
        }
        cudaGridDependencySynchronize();     // wait: g_Wt/g_dis (upstream chain)
    } else {
        cudaGridDependencySynchronize();     // wait: A from predecessor aggregate
        const uint4* Ag = (const uint4*)((const __half*)Avoid + (size_t)(row0 + ldRow) * D + ldCol);
        uint4 z = make_uint4(0u, 0u, 0u, 0u);
#pragma unroll
        for (int j = 0; j < 8; j++)
            *(uint4*)(sA + ldRow * PADA + ldCol + 8 * j) = okA ? Ag[j] : z;
    }
    {
        const uint4* Wg = (const uint4*)(Wt + ldRow * D + ldCol);
#pragma unroll
        for (int j = 0; j < 8; j++)
            *(uint4*)(sW + ldRow * PADA + ldCol + 8 * j) = Wg[j];
    }
    __syncthreads();

    float acc[2][8][4];
#pragma unroll
    for (int mt = 0; mt < 2; mt++)
#pragma unroll
        for (int nt = 0; nt < 8; nt++)
#pragma unroll
            for (int q = 0; q < 4; q++) acc[mt][nt][q] = 0.f;

#pragma unroll
    for (int ks = 0; ks < 8; ks++) {
        int acol = ks * 16 + ((lane >> 4) << 3);
        int lrow = lane & 15;
        uint32_t af[2][4];
        ldsm_x4(af[0], aA + (uint32_t)(((m0      + lrow) * PADA + acol) * 2));
        ldsm_x4(af[1], aA + (uint32_t)(((m0 + 16 + lrow) * PADA + acol) * 2));
        uint32_t bf_[4][4];
#pragma unroll
        for (int bt = 0; bt < 4; bt++)
            ldsm_x4(bf_[bt], aW + (uint32_t)(((n0 + bt * 16 + lrow) * PADA + acol) * 2));
#pragma unroll
        for (int mt = 0; mt < 2; mt++)
#pragma unroll
            for (int bt = 0; bt < 4; bt++) {
                mma_fp16(acc[mt][2 * bt],     af[mt], bf_[bt][0], bf_[bt][2]);
                mma_fp16(acc[mt][2 * bt + 1], af[mt], bf_[bt][1], bf_[bt][3]);
            }
    }

    // main compute done — let the next kernel start its launch/prologue
    cudaTriggerProgrammaticLaunchCompletion();

#pragma unroll
    for (int mt = 0; mt < 2; mt++) {
        int r0 = row0 + m0 + mt * 16 + (lane >> 2);
        int r1 = r0 + 8;
        float d0 = (r0 < n) ? g_dis[r0] : 0.f;
        float d1 = (r1 < n) ? g_dis[r1] : 0.f;
#pragma unroll
        for (int nt = 0; nt < 8; nt++) {
            int col = n0 + nt * 8 + (lane & 3) * 2;
            if (r0 < n)
                *(__half2*)(G + (size_t)r0 * D + col) =
                    __floats2half2_rn(acc[mt][nt][0] * d0, acc[mt][nt][1] * d0);
            if (r1 < n)
                *(__half2*)(G + (size_t)r1 * D + col) =
                    __floats2half2_rn(acc[mt][nt][2] * d1, acc[mt][nt][3] * d1);
        }
    }
}

// ---------------- aggregation core (fp32 accum over fp16 gathers) ------------
__device__ __forceinline__ float4 agg_node(const uint2* __restrict__ G8,
                                           int node, int lane) {
    uint2 sr = G8[(size_t)node * 32 + lane];     // self term
    float2 s0 = __half22float2(*(const __half2*)&sr.x);
    float2 s1 = __half22float2(*(const __half2*)&sr.y);
    float4 acc = make_float4(s0.x, s0.y, s1.x, s1.y);

    int start = g_offsets[node];
    int cnt   = g_counts[node];
    int e = 0;
    for (; e + 4 <= cnt; e += 4) {
        int i0 = g_adj[start + e + 0];
        int i1 = g_adj[start + e + 1];
        int i2 = g_adj[start + e + 2];
        int i3 = g_adj[start + e + 3];
        uint2 r0 = G8[(size_t)i0 * 32 + lane];
        uint2 r1 = G8[(size_t)i1 * 32 + lane];
        uint2 r2 = G8[(size_t)i2 * 32 + lane];
        uint2 r3 = G8[(size_t)i3 * 32 + lane];
        float2 a, b;
        a = __half22float2(*(const __half2*)&r0.x); b = __half22float2(*(const __half2*)&r0.y);
        acc.x += a.x; acc.y += a.y; acc.z += b.x; acc.w += b.y;
        a = __half22float2(*(const __half2*)&r1.x); b = __half22float2(*(const __half2*)&r1.y);
        acc.x += a.x; acc.y += a.y; acc.z += b.x; acc.w += b.y;
        a = __half22float2(*(const __half2*)&r2.x); b = __half22float2(*(const __half2*)&r2.y);
        acc.x += a.x; acc.y += a.y; acc.z += b.x; acc.w += b.y;
        a = __half22float2(*(const __half2*)&r3.x); b = __half22float2(*(const __half2*)&r3.y);
        acc.x += a.x; acc.y += a.y; acc.z += b.x; acc.w += b.y;
    }
    for (; e < cnt; e++) {
        int s = g_adj[start + e];
        uint2 r = G8[(size_t)s * 32 + lane];
        float2 a = __half22float2(*(const __half2*)&r.x);
        float2 b = __half22float2(*(const __half2*)&r.y);
        acc.x += a.x; acc.y += a.y; acc.z += b.x; acc.w += b.y;
    }
    return acc;
}

// intermediate layers: fp16 activation out, relu
__global__ void k_aggregate_h(const __half* __restrict__ G,
                              const float* __restrict__ bias,
                              __half* __restrict__ out, int n) {
    cudaGridDependencySynchronize();        // wait: messages from predecessor gemm
    int warp = (blockIdx.x * blockDim.x + threadIdx.x) >> 5;
    if (warp >= n) return;                  // exited CTAs count toward trigger
    int lane = threadIdx.x & 31;

    float4 acc = agg_node((const uint2*)G, warp, lane);
    cudaTriggerProgrammaticLaunchCompletion();
    float ds = g_dis[warp];
    float4 b4 = ((const float4*)bias)[lane];
    float4 o;
    o.x = fmaxf(fmaf(ds, acc.x, b4.x), 0.f);
    o.y = fmaxf(fmaf(ds, acc.y, b4.y), 0.f);
    o.z = fmaxf(fmaf(ds, acc.z, b4.z), 0.f);
    o.w = fmaxf(fmaf(ds, acc.w, b4.w), 0.f);
    uint2 p;
    *(__half2*)&p.x = __floats2half2_rn(o.x, o.y);
    *(__half2*)&p.y = __floats2half2_rn(o.z, o.w);
    ((uint2*)out)[(size_t)warp * 32 + lane] = p;
}

// final layer: fp32 out, no relu
__global__ void k_aggregate_f(const __half* __restrict__ G,
                              const float* __restrict__ bias,
                              float* __restrict__ out, int n) {
    cudaGridDependencySynchronize();
    int warp = (blockIdx.x * blockDim.x + threadIdx.x) >> 5;
    if (warp >= n) return;
    int lane = threadIdx.x & 31;

    float4 acc = agg_node((const uint2*)G, warp, lane);
    float ds = g_dis[warp];
    float4 b4 = ((const float4*)bias)[lane];
    float4 o;
    o.x = fmaf(ds, acc.x, b4.x);
    o.y = fmaf(ds, acc.y, b4.y);
    o.z = fmaf(ds, acc.z, b4.z);
    o.w = fmaf(ds, acc.w, b4.w);
    ((float4*)out)[(size_t)warp * 32 + lane] = o;
}

// ---------------- PDL launch helper ------------------------------------------
template <typename F, typename... Args>
static inline void launch_pdl(F kern, dim3 grid, dim3 block, size_t smemBytes, Args... args) {
    cudaLaunchConfig_t cfg = {};
    cfg.gridDim = grid;
    cfg.blockDim = block;
    cfg.dynamicSmemBytes = smemBytes;
    cfg.stream = (cudaStream_t)0;
    cudaLaunchAttribute attr[1];
    attr[0].id = cudaLaunchAttributeProgrammaticStreamSerialization;
    attr[0].val.programmaticStreamSerializationAllowed = 1;
    cfg.attrs = attr;
    cfg.numAttrs = 1;
    cudaLaunchKernelEx(&cfg, kern, args...);
}

// ---------------- launch -----------------------------------------------------
extern "C" void kernel_launch(void* const* d_in, const int* in_sizes, int n_in,
                              void* d_out, int out_size) {
    const float* x  = (const float*)d_in[0];
    const int*   ei = (const int*)d_in[1];
    const float* W0 = (const float*)d_in[2];
    const float* b0 = (const float*)d_in[3];
    const float* W1 = (const float*)d_in[4];
    const float* b1 = (const float*)d_in[5];
    const float* W2 = (const float*)d_in[6];
    const float* b2 = (const float*)d_in[7];

    int n = in_sizes[0] / D;
    int e = in_sizes[1] / 2;
    const int* src = ei;
    const int* dst = ei + e;

    __half* bufG = nullptr; __half* bufH = nullptr;
    __half* wt = nullptr;
    cudaGetSymbolAddress((void**)&bufG, g_bufG);
    cudaGetSymbolAddress((void**)&bufH, g_bufH);
    cudaGetSymbolAddress((void**)&wt, g_Wt);
    float* out = (float*)d_out;

    cudaFuncSetAttribute(k_gemm<1>, cudaFuncAttributeMaxDynamicSharedMemorySize, G_SMEM);
    cudaFuncSetAttribute(k_gemm<0>, cudaFuncAttributeMaxDynamicSharedMemorySize, G_SMEM);

    int gn = (n + 255) / 256;
    int ge = (e + 255) / 256;
    int nb = (n + 1023) / 1024;

    k_setup<<<gn + 192, 256>>>(n, gn, W0, W1, W2);
    launch_pdl(k_count, dim3(ge), dim3(256), 0, dst, e);
    launch_pdl(k_scan,  dim3(nb), dim3(1024), 0, n);
    launch_pdl(k_fill,  dim3(ge), dim3(256), 0, src, dst, e);

    int ggemm = (n + 127) / 128;
    int gagg  = (n * 32 + 255) / 256;

    launch_pdl(k_gemm<1>,     dim3(ggemm), dim3(256), (size_t)G_SMEM,
               (const void*)x, (const __half*)(wt + 0 * D * D), bufG, n);
    launch_pdl(k_aggregate_h, dim3(gagg), dim3(256), (size_t)0,
               (const __half*)bufG, b0, bufH, n);
    launch_pdl(k_gemm<0>,     dim3(ggemm), dim3(256), (size_t)G_SMEM,
               (const void*)bufH, (const __half*)(wt + 1 * D * D), bufG, n);
    launch_pdl(k_aggregate_h, dim3(gagg), dim3(256), (size_t)0,
               (const __half*)bufG, b1, bufH, n);
    launch_pdl(k_gemm<0>,     dim3(ggemm), dim3(256), (size_t)G_SMEM,
               (const void*)bufH, (const __half*)(wt + 2 * D * D), bufG, n);
    launch_pdl(k_aggregate_f, dim3(gagg), dim3(256), (size_t)0,
               (const __half*)bufG, b2, out, n);
}